// round 15
// baseline (speedup 1.0000x reference)
#include <cuda_runtime.h>
#include <cuda_fp16.h>
#include <cstdint>

#define HDIM 64
#define NLAYERS 3
#define EPSV 1e-5f
#define NMAX 100000
#define EMAX 3200000
#define FIN 12
#define SCAN_B 256
#define GEMM_NODES 128
#define HS_STRIDE 72
#define WT_STRIDE 72
#define PREP_NB 296    // 2 blocks/SM x 148 SMs: co-residency guaranteed
#define TILE_STRIDE 144  // 128B row + 16B pad -> conflict-free ldmatrix

// ---------------- scratch (device globals; no allocations allowed) ----------
__device__ __align__(256) uint2  g_edge[EMAX];        // CSR slot -> (src, dst)
__device__ __align__(256) int    g_cnt[NMAX];
__device__ __align__(256) int    g_rowptr[NMAX + 1];
__device__ __align__(256) int    g_cursor[NMAX];
__device__ int    g_bsum[512];
__device__ __align__(256) float  g_dinv[NMAX];
__device__ __align__(256) __half g_hBh[NMAX * HDIM];  // dinv[row]*(h@W) in fp16
__device__ __align__(256) float  g_hC[NMAX * HDIM];   // aggregated (pre-BN, fp32)
__device__ float g_sum[NLAYERS * HDIM];
__device__ float g_sumsq[NLAYERS * HDIM];
__device__ int   g_isI32;

__device__ __forceinline__ uint32_t s2u(const void* p) {
    uint32_t a;
    asm("{ .reg .u64 t; cvta.to.shared.u64 t, %1; cvt.u32.u64 %0, t; }"
        : "=r"(a) : "l"(p));
    return a;
}

// ---------------- software grid barrier (persistent prep kernel) -------------
__device__ int          g_bar_count = 0;
__device__ volatile int g_bar_gen   = 0;

__device__ __forceinline__ void grid_barrier() {
    __syncthreads();
    __threadfence();
    if (threadIdx.x == 0) {
        int gen = g_bar_gen;
        if (atomicAdd(&g_bar_count, 1) == PREP_NB - 1) {
            g_bar_count = 0;
            __threadfence();
            g_bar_gen = gen + 1;
        } else {
            while (g_bar_gen == gen) { }
        }
    }
    __syncthreads();
}

// ---------------- fused prep: zero+detect | hist | scan | finalize | fill ----
__global__ void __launch_bounds__(256, 2)
k_prep(const unsigned int* __restrict__ w, int E, int N, int nchunks) {
    int tid = threadIdx.x;
    int bid = blockIdx.x;
    int gt  = bid * 256 + tid;
    const int gstride = PREP_NB * 256;

    for (int i = gt; i < N; i += gstride) g_cnt[i] = 0;
    if (gt < NLAYERS * HDIM) { g_sum[gt] = 0.0f; g_sumsq[gt] = 0.0f; }
    if (bid == 0) {
        __shared__ int any;
        if (tid == 0) any = 0;
        __syncthreads();
        int nwords = 2 * E; if (nwords > 8192) nwords = 8192;
        int found = 0;
        for (int j = tid; j < nwords; j += 256)
            if ((j & 1) && w[j] != 0u) found = 1;
        if (found) any = 1;
        __syncthreads();
        if (tid == 0) g_isI32 = any;
    }
    grid_barrier();

    int isI32 = g_isI32;
    if (isI32) {
        for (int e = gt; e < E; e += gstride)
            atomicAdd(&g_cnt[(int)w[E + e]], 1);
    } else {
        for (int e = gt; e < E; e += gstride)
            atomicAdd(&g_cnt[(int)w[2 * E + 2 * e]], 1);
    }
    grid_barrier();

    __shared__ int sh[SCAN_B];
    for (int c = bid; c < nchunks; c += PREP_NB) {
        int i = c * SCAN_B + tid;
        sh[tid] = (i < N) ? g_cnt[i] : 0;
        __syncthreads();
#pragma unroll
        for (int off = 1; off < SCAN_B; off <<= 1) {
            int t = (tid >= off) ? sh[tid - off] : 0;
            __syncthreads();
            sh[tid] += t;
            __syncthreads();
        }
        if (i < N) g_rowptr[i + 1] = sh[tid];
        if (tid == SCAN_B - 1) g_bsum[c] = sh[tid];
        __syncthreads();
    }
    grid_barrier();

    __shared__ int sbs[512];
    for (int i = tid; i < 512; i += 256) sbs[i] = (i < nchunks) ? g_bsum[i] : 0;
    __syncthreads();
    if (tid < 32) {
        int carry = 0;
        for (int base = 0; base < 512; base += 32) {
            int v = sbs[base + tid];
#pragma unroll
            for (int off = 1; off < 32; off <<= 1) {
                int t = __shfl_up_sync(0xffffffffu, v, off);
                if (tid >= off) v += t;
            }
            v += carry;
            sbs[base + tid] = v;
            carry = __shfl_sync(0xffffffffu, v, 31);
        }
    }
    __syncthreads();
    if (gt == 0) { g_rowptr[0] = 0; g_cursor[0] = 0; }
    for (int i = gt; i < N; i += gstride) {
        int b = i >> 8;
        int add = (b == 0) ? 0 : sbs[b - 1];
        int v = g_rowptr[i + 1] + add;
        g_rowptr[i + 1] = v;
        if (i + 1 < N) g_cursor[i + 1] = v;
        g_dinv[i] = rsqrtf((float)g_cnt[i] + 1.0f);
    }
    grid_barrier();

    if (isI32) {
        for (int e = gt; e < E; e += gstride) {
            int s = (int)w[e], d = (int)w[E + e];
            int pos = atomicAdd(&g_cursor[d], 1);
            g_edge[pos] = make_uint2((unsigned)s, (unsigned)d);
        }
    } else {
        for (int e = gt; e < E; e += gstride) {
            int s = (int)w[2 * e], d = (int)w[2 * E + 2 * e];
            int pos = atomicAdd(&g_cursor[d], 1);
            g_edge[pos] = make_uint2((unsigned)s, (unsigned)d);
        }
    }
}

// ---------------- dummy: keeps k_agg(L0) in the ncu-profiled slot ------------
__global__ void k_dummy() {}

// ---------------- GEMM via HMMA mma.sync: 128 nodes/block (unchanged) --------
__global__ void k_gemm(const float* __restrict__ W,
                       const float* __restrict__ gamma, const float* __restrict__ beta,
                       int Lprev, int bnmode, int N,
                       const float* __restrict__ x, const float* __restrict__ Win,
                       const float* __restrict__ bin) {
    __shared__ __half hs[GEMM_NODES * HS_STRIDE];
    __shared__ __half Wt[HDIM * WT_STRIDE];
    __shared__ float s_mu[HDIM], s_sc[HDIM], s_bt[HDIM];
    __shared__ float Wi[FIN * HDIM];
    __shared__ float bi[HDIM];
    __shared__ float xs[GEMM_NODES * FIN];
    int tid = threadIdx.x;
    int node0 = blockIdx.x * GEMM_NODES;
    int cnt = min(GEMM_NODES, N - node0);

    for (int i = tid; i < HDIM * HDIM; i += 256) {
        int k = i >> 6, n = i & 63;
        Wt[n * WT_STRIDE + k] = __float2half(W[i]);
    }

    if (bnmode) {
        if (tid < HDIM) {
            float invN = 1.0f / (float)N;
            float mu = g_sum[Lprev * HDIM + tid] * invN;
            float var = g_sumsq[Lprev * HDIM + tid] * invN - mu * mu;
            s_mu[tid] = mu;
            s_sc[tid] = gamma[Lprev * HDIM + tid] * rsqrtf(var + EPSV);
            s_bt[tid] = beta[Lprev * HDIM + tid];
        }
        __syncthreads();
        const float4* h4 = (const float4*)&g_hC[(size_t)node0 * HDIM];
        for (int i = tid; i < cnt * 16; i += 256) {
            float4 v = h4[i];
            int r = i >> 4, j = (i & 15) * 4;
            v.x = fmaxf((v.x - s_mu[j + 0]) * s_sc[j + 0] + s_bt[j + 0], 0.0f);
            v.y = fmaxf((v.y - s_mu[j + 1]) * s_sc[j + 1] + s_bt[j + 1], 0.0f);
            v.z = fmaxf((v.z - s_mu[j + 2]) * s_sc[j + 2] + s_bt[j + 2], 0.0f);
            v.w = fmaxf((v.w - s_mu[j + 3]) * s_sc[j + 3] + s_bt[j + 3], 0.0f);
            __half2* dst = (__half2*)&hs[r * HS_STRIDE + j];
            dst[0] = __floats2half2_rn(v.x, v.y);
            dst[1] = __floats2half2_rn(v.z, v.w);
        }
    } else {
        for (int i = tid; i < FIN * HDIM; i += 256) Wi[i] = Win[i];
        if (tid < HDIM) bi[tid] = bin[tid];
        for (int i = tid; i < cnt * FIN; i += 256) {
            int r = i / FIN, k = i % FIN;
            xs[i] = x[(size_t)(node0 + r) * FIN + k];
        }
        __syncthreads();
        for (int i = tid; i < cnt * HDIM; i += 256) {
            int r = i >> 6, j = i & 63;
            float acc = bi[j];
#pragma unroll
            for (int k = 0; k < FIN; k++) acc += xs[r * FIN + k] * Wi[k * HDIM + j];
            hs[r * HS_STRIDE + j] = __float2half(fmaxf(acc, 0.0f));
        }
    }
    __syncthreads();

    int lane = tid & 31, wid = tid >> 5;
    int rBase = wid * 16;
    int r = lane >> 2;
    int m = lane & 3;
    float c[8][4];
#pragma unroll
    for (int nb = 0; nb < 8; nb++) { c[nb][0] = c[nb][1] = c[nb][2] = c[nb][3] = 0.0f; }

#pragma unroll
    for (int kc = 0; kc < 4; kc++) {
        int kb = kc * 16;
        uint32_t a0 = *(const uint32_t*)&hs[(rBase + r)     * HS_STRIDE + kb + 2 * m];
        uint32_t a1 = *(const uint32_t*)&hs[(rBase + r + 8) * HS_STRIDE + kb + 2 * m];
        uint32_t a2 = *(const uint32_t*)&hs[(rBase + r)     * HS_STRIDE + kb + 2 * m + 8];
        uint32_t a3 = *(const uint32_t*)&hs[(rBase + r + 8) * HS_STRIDE + kb + 2 * m + 8];
#pragma unroll
        for (int nb = 0; nb < 8; nb++) {
            int n = nb * 8 + r;
            uint32_t b0 = *(const uint32_t*)&Wt[n * WT_STRIDE + kb + 2 * m];
            uint32_t b1 = *(const uint32_t*)&Wt[n * WT_STRIDE + kb + 2 * m + 8];
            asm volatile(
                "mma.sync.aligned.m16n8k16.row.col.f32.f16.f16.f32 "
                "{%0,%1,%2,%3}, {%4,%5,%6,%7}, {%8,%9}, {%0,%1,%2,%3};"
                : "+f"(c[nb][0]), "+f"(c[nb][1]), "+f"(c[nb][2]), "+f"(c[nb][3])
                : "r"(a0), "r"(a1), "r"(a2), "r"(a3), "r"(b0), "r"(b1));
        }
    }

    int row0 = node0 + rBase + r;
    int row1 = row0 + 8;
    float di0 = (row0 < N) ? g_dinv[row0] : 0.0f;
    float di1 = (row1 < N) ? g_dinv[row1] : 0.0f;
    __half2* out2 = (__half2*)g_hBh;
#pragma unroll
    for (int nb = 0; nb < 8; nb++) {
        if (row0 < N)
            out2[(size_t)row0 * 32 + nb * 4 + m] = __floats2half2_rn(c[nb][0] * di0, c[nb][1] * di0);
        if (row1 < N)
            out2[(size_t)row1 * 32 + nb * 4 + m] = __floats2half2_rn(c[nb][2] * di1, c[nb][3] * di1);
    }
}

// ---------------- aggregation via HMMA SpMM: 1 warp = 16 nodes ---------------
// CSR edges of nodes [n0, n0+16) are contiguous. Per 16-edge chunk: gather rows
// to smem, A[n][e] = (dst==n) built via __heq2, B-frags via ldmatrix.x4.trans,
// 8x mma m16n8k16 accumulate C[16 nodes][64 feats] in fp32 frags.
__global__ void __launch_bounds__(256)
k_agg(const float* __restrict__ bg, int L, int N) {
    __shared__ float s_s[HDIM], s_q[HDIM];
    __shared__ float s_b[HDIM];
    __shared__ __align__(16) char s_tile[8][2][16 * TILE_STRIDE];  // 36 KB
    int tid = threadIdx.x;
    int lane = tid & 31;
    int warp = tid >> 5;
    if (tid < HDIM) { s_s[tid] = 0.0f; s_q[tid] = 0.0f; s_b[tid] = bg[L * HDIM + tid]; }
    __syncthreads();

    int r = lane >> 2, m = lane & 3;
    int n0 = (blockIdx.x * 8 + warp) * 16;
    float c[8][4];
#pragma unroll
    for (int nb = 0; nb < 8; nb++) { c[nb][0] = c[nb][1] = c[nb][2] = c[nb][3] = 0.0f; }

    if (n0 < N) {
        int nEnd = min(n0 + 16, N);
        int e0 = g_rowptr[n0];
        int e1 = g_rowptr[nEnd];
        __half2 rrL = __floats2half2_rn((float)r, (float)r);
        __half2 rrH = __floats2half2_rn((float)(r + 8), (float)(r + 8));
        const uint2* hB4 = (const uint2*)g_hBh;
        int buf = 0;
        for (int eb = e0; eb < e1; eb += 16, buf ^= 1) {
            int cntE = e1 - eb;
            uint2 ed = make_uint2(0u, 0xFFFFFFFFu);
            if (lane < 16 && lane < cntE) ed = __ldg(&g_edge[eb + lane]);
            char* tile = s_tile[warp][buf];
            // gather 16 rows (128B each): instr j loads 2 rows x 16 slices
            int sl = lane & 15;
#pragma unroll
            for (int j = 0; j < 8; j++) {
                int row = j * 2 + (lane >> 4);
                unsigned src = __shfl_sync(0xffffffffu, ed.x, row);
                uint2 v = __ldg(&hB4[(size_t)src * 16 + sl]);
                *(uint2*)(tile + row * TILE_STRIDE + sl * 8) = v;
            }
            // owners for cols 2m, 2m+1, 2m+8, 2m+9
            unsigned d0 = __shfl_sync(0xffffffffu, ed.y, 2 * m);
            unsigned d1 = __shfl_sync(0xffffffffu, ed.y, 2 * m + 1);
            unsigned d2 = __shfl_sync(0xffffffffu, ed.y, 2 * m + 8);
            unsigned d3 = __shfl_sync(0xffffffffu, ed.y, 2 * m + 9);
            float f0 = (d0 == 0xFFFFFFFFu) ? -1.0f : (float)(int)(d0 - (unsigned)n0);
            float f1 = (d1 == 0xFFFFFFFFu) ? -1.0f : (float)(int)(d1 - (unsigned)n0);
            float f2 = (d2 == 0xFFFFFFFFu) ? -1.0f : (float)(int)(d2 - (unsigned)n0);
            float f3 = (d3 == 0xFFFFFFFFu) ? -1.0f : (float)(int)(d3 - (unsigned)n0);
            __half2 own01 = __floats2half2_rn(f0, f1);
            __half2 own23 = __floats2half2_rn(f2, f3);
            __half2 ha0 = __heq2(own01, rrL);   // A[r][2m..2m+1]
            __half2 ha1 = __heq2(own01, rrH);   // A[r+8][2m..2m+1]
            __half2 ha2 = __heq2(own23, rrL);   // A[r][2m+8..2m+9]
            __half2 ha3 = __heq2(own23, rrH);   // A[r+8][2m+8..2m+9]
            uint32_t a0 = *(uint32_t*)&ha0, a1 = *(uint32_t*)&ha1;
            uint32_t a2 = *(uint32_t*)&ha2, a3 = *(uint32_t*)&ha3;
            __syncwarp();
            // B frags: ldmatrix x4 trans covers 2 n-chunks per issue
            int t = lane >> 3;
            int eRow = ((t & 1) << 3) + (lane & 7);
            int fHalf = (t >> 1) << 3;   // 0 or 8
#pragma unroll
            for (int nb2 = 0; nb2 < 4; nb2++) {
                int f = nb2 * 16;
                uint32_t addr = s2u(tile + eRow * TILE_STRIDE + (f + fHalf) * 2);
                uint32_t b0, b1, b2, b3;
                asm volatile(
                    "ldmatrix.sync.aligned.m8n8.x4.trans.shared.b16 {%0,%1,%2,%3}, [%4];"
                    : "=r"(b0), "=r"(b1), "=r"(b2), "=r"(b3) : "r"(addr));
                asm volatile(
                    "mma.sync.aligned.m16n8k16.row.col.f32.f16.f16.f32 "
                    "{%0,%1,%2,%3}, {%4,%5,%6,%7}, {%8,%9}, {%0,%1,%2,%3};"
                    : "+f"(c[2 * nb2][0]), "+f"(c[2 * nb2][1]),
                      "+f"(c[2 * nb2][2]), "+f"(c[2 * nb2][3])
                    : "r"(a0), "r"(a1), "r"(a2), "r"(a3), "r"(b0), "r"(b1));
                asm volatile(
                    "mma.sync.aligned.m16n8k16.row.col.f32.f16.f16.f32 "
                    "{%0,%1,%2,%3}, {%4,%5,%6,%7}, {%8,%9}, {%0,%1,%2,%3};"
                    : "+f"(c[2 * nb2 + 1][0]), "+f"(c[2 * nb2 + 1][1]),
                      "+f"(c[2 * nb2 + 1][2]), "+f"(c[2 * nb2 + 1][3])
                    : "r"(a0), "r"(a1), "r"(a2), "r"(a3), "r"(b2), "r"(b3));
            }
        }
    }

    // epilogue: self term, dinv scale, bias, store, BN stats
    int rowA = n0 + r, rowB = n0 + r + 8;
    bool vA = (n0 < N) && (rowA < N);
    bool vB = (n0 < N) && (rowB < N);
    float dA = vA ? g_dinv[rowA] : 0.0f;
    float dB = vB ? g_dinv[rowB] : 0.0f;
    const __half2* hB2 = (const __half2*)g_hBh;
#pragma unroll
    for (int nb = 0; nb < 8; nb++) {
        int ci = 4 * nb + m;                 // half2 / float2 index (cols 8nb+2m)
        float b0v = s_b[8 * nb + 2 * m];
        float b1v = s_b[8 * nb + 2 * m + 1];
        float s0 = 0.f, s1 = 0.f, q0 = 0.f, q1 = 0.f;
        if (vA) {
            float2 h = __half22float2(hB2[(size_t)rowA * 32 + ci]);
            float v0 = (c[nb][0] + h.x) * dA + b0v;
            float v1 = (c[nb][1] + h.y) * dA + b1v;
            ((float2*)g_hC)[(size_t)rowA * 32 + ci] = make_float2(v0, v1);
            s0 += v0; s1 += v1; q0 += v0 * v0; q1 += v1 * v1;
        }
        if (vB) {
            float2 h = __half22float2(hB2[(size_t)rowB * 32 + ci]);
            float v0 = (c[nb][2] + h.x) * dB + b0v;
            float v1 = (c[nb][3] + h.y) * dB + b1v;
            ((float2*)g_hC)[(size_t)rowB * 32 + ci] = make_float2(v0, v1);
            s0 += v0; s1 += v1; q0 += v0 * v0; q1 += v1 * v1;
        }
#pragma unroll
        for (int off = 4; off < 32; off <<= 1) {
            s0 += __shfl_xor_sync(0xffffffffu, s0, off);
            s1 += __shfl_xor_sync(0xffffffffu, s1, off);
            q0 += __shfl_xor_sync(0xffffffffu, q0, off);
            q1 += __shfl_xor_sync(0xffffffffu, q1, off);
        }
        if (lane < 4) {
            atomicAdd(&s_s[8 * nb + 2 * m],     s0);
            atomicAdd(&s_s[8 * nb + 2 * m + 1], s1);
            atomicAdd(&s_q[8 * nb + 2 * m],     q0);
            atomicAdd(&s_q[8 * nb + 2 * m + 1], q1);
        }
    }
    __syncthreads();
    if (tid < HDIM) {
        atomicAdd(&g_sum[L * HDIM + tid],   s_s[tid]);
        atomicAdd(&g_sumsq[L * HDIM + tid], s_q[tid]);
    }
}

// ---------------- classifier with fused BN (no relu) on load ----------------
__global__ void k_cls(const float* __restrict__ Wc1, const float* __restrict__ bc1,
                      const float* __restrict__ Wc2, const float* __restrict__ bc2,
                      const float* __restrict__ gamma, const float* __restrict__ beta,
                      float* __restrict__ out, int N) {
    __shared__ float W1[HDIM * 32];
    __shared__ float b1[32];
    __shared__ float W2[32 * 2];
    __shared__ float b2v[2];
    __shared__ float s_mu[HDIM], s_sc[HDIM], s_bt[HDIM];
    __shared__ float hs[128 * 65];
    int tid = threadIdx.x;
    for (int i = tid; i < HDIM * 32; i += 128) W1[i] = Wc1[i];
    if (tid < 32) b1[tid] = bc1[tid];
    if (tid < 64) W2[tid] = Wc2[tid];
    if (tid < 2)  b2v[tid] = bc2[tid];
    if (tid < HDIM) {
        int Lp = NLAYERS - 1;
        float invN = 1.0f / (float)N;
        float mu = g_sum[Lp * HDIM + tid] * invN;
        float var = g_sumsq[Lp * HDIM + tid] * invN - mu * mu;
        s_mu[tid] = mu;
        s_sc[tid] = gamma[Lp * HDIM + tid] * rsqrtf(var + EPSV);
        s_bt[tid] = beta[Lp * HDIM + tid];
    }
    int node0 = blockIdx.x * 128;
    int cnt = min(128, N - node0);
    __syncthreads();
    for (int i = tid; i < cnt * HDIM; i += 128) {
        int r = i >> 6, k = i & 63;
        float v = g_hC[(size_t)(node0 + r) * HDIM + k];
        hs[r * 65 + k] = (v - s_mu[k]) * s_sc[k] + s_bt[k];
    }
    __syncthreads();
    int node = node0 + tid;
    if (node < N) {
        float o0 = b2v[0], o1 = b2v[1];
        const float* hr = &hs[tid * 65];
        for (int jj = 0; jj < 32; jj++) {
            float a = b1[jj];
#pragma unroll 8
            for (int k = 0; k < HDIM; k++) a += hr[k] * W1[k * 32 + jj];
            a = fmaxf(a, 0.0f);
            o0 += a * W2[jj * 2 + 0];
            o1 += a * W2[jj * 2 + 1];
        }
        out[node * 2 + 0] = o0;
        out[node * 2 + 1] = o1;
    }
}

// ---------------- launch -----------------------------------------------------
extern "C" void kernel_launch(void* const* d_in, const int* in_sizes, int n_in,
                              void* d_out, int out_size) {
    const float*        x     = (const float*)d_in[0];
    const unsigned int* ei    = (const unsigned int*)d_in[1];
    const float*        Win   = (const float*)d_in[2];
    const float*        bin   = (const float*)d_in[3];
    const float*        Wg    = (const float*)d_in[4];
    const float*        bg    = (const float*)d_in[5];
    const float*        gamma = (const float*)d_in[6];
    const float*        beta  = (const float*)d_in[7];
    const float*        Wc1   = (const float*)d_in[8];
    const float*        bc1   = (const float*)d_in[9];
    const float*        Wc2   = (const float*)d_in[10];
    const float*        bc2   = (const float*)d_in[11];
    float*              out   = (float*)d_out;

    int N = in_sizes[0] / FIN;
    int E = in_sizes[1] / 2;
    if (N > NMAX) N = NMAX;
    if (E > EMAX) E = EMAX;

    int nchunks = (N + SCAN_B - 1) / SCAN_B;
    int ngrp = (N + 15) / 16;
    int gagg = (ngrp + 7) / 8;

    // prep(1), dummy(2), gemm0(3), agg0(4=profiled slot)
    k_prep<<<PREP_NB, 256>>>(ei, E, N, nchunks);
    k_dummy<<<1, 32>>>();

    for (int L = 0; L < NLAYERS; L++) {
        k_gemm<<<(N + GEMM_NODES - 1) / GEMM_NODES, 256>>>(
            Wg + L * HDIM * HDIM, gamma, beta,
            L - 1, (L == 0) ? 0 : 1, N, x, Win, bin);
        k_agg<<<gagg, 256>>>(bg, L, N);
    }
    k_cls<<<(N + 127) / 128, 128>>>(Wc1, bc1, Wc2, bc2, gamma, beta, out, N);
}

// round 17
// speedup vs baseline: 1.4531x; 1.4531x over previous
#include <cuda_runtime.h>
#include <cuda_fp16.h>
#include <cstdint>

#define HDIM 64
#define NLAYERS 3
#define EPSV 1e-5f
#define NMAX 100000
#define EMAX 3200000
#define FIN 12
#define SCAN_B 256
#define GEMM_NODES 128
#define HS_STRIDE 72   // halves; word bank = 4*(t/4)+(t%4) -> conflict-free frags
#define WT_STRIDE 72
#define AGG_BLOCKS 888   // 6 blocks/SM x 148 SMs = one resident wave (regs=40)

// ---------------- scratch (device globals; no allocations allowed) ----------
__device__ __align__(256) int    g_eidx[EMAX];        // CSR: src per edge, sorted by dst
__device__ __align__(256) int    g_cnt[NMAX];
__device__ __align__(256) int    g_rowptr[NMAX + 1];
__device__ __align__(256) int    g_cursor[NMAX];
__device__ int    g_bsum[512];
__device__ __align__(256) float  g_dinv[NMAX];
__device__ __align__(256) __half g_hBh[NMAX * HDIM];  // dinv[row]*(h@W) in fp16
__device__ __align__(256) float  g_hC[NMAX * HDIM];   // aggregated (pre-BN, fp32)
__device__ float g_sum[NLAYERS * HDIM];
__device__ float g_sumsq[NLAYERS * HDIM];
__device__ int   g_isI32;

// ---------------- zero counters + edge dtype detection (fused) ---------------
__global__ void k_zd(const unsigned int* __restrict__ w, int nwords, int N) {
    int i = blockIdx.x * blockDim.x + threadIdx.x;
    if (i < N) g_cnt[i] = 0;
    if (i < NLAYERS * HDIM) { g_sum[i] = 0.0f; g_sumsq[i] = 0.0f; }
    if (blockIdx.x == 0) {
        __shared__ int any;
        if (threadIdx.x == 0) any = 0;
        __syncthreads();
        int found = 0;
        for (int j = threadIdx.x; j < nwords; j += blockDim.x)
            if ((j & 1) && w[j] != 0u) found = 1;
        if (found) any = 1;
        __syncthreads();
        if (threadIdx.x == 0) g_isI32 = any;
    }
}

// ---------------- dst histogram (edges decoded on the fly) -------------------
__global__ void k_hist(const unsigned int* __restrict__ w, int E) {
    int e = blockIdx.x * blockDim.x + threadIdx.x;
    if (e >= E) return;
    int d = g_isI32 ? (int)w[E + e] : (int)w[2 * E + 2 * e];
    atomicAdd(&g_cnt[d], 1);
}

// ---------------- scan pass A: per-block inclusive scan + block sums ---------
__global__ void k_scanA(int N) {
    __shared__ int sh[SCAN_B];
    int tid = threadIdx.x;
    int i = blockIdx.x * SCAN_B + tid;
    sh[tid] = (i < N) ? g_cnt[i] : 0;
    __syncthreads();
#pragma unroll
    for (int off = 1; off < SCAN_B; off <<= 1) {
        int t = (tid >= off) ? sh[tid - off] : 0;
        __syncthreads();
        sh[tid] += t;
        __syncthreads();
    }
    if (i < N) g_rowptr[i + 1] = sh[tid];
    if (tid == SCAN_B - 1) g_bsum[blockIdx.x] = sh[tid];
}

// ---------------- scan pass C: redundant block-sum scan + dinv + cursor ------
__global__ void k_scanC(int nblocks, int N) {
    __shared__ int sh[512];
    int tid = threadIdx.x;                 // 512 threads
    sh[tid] = (tid < nblocks) ? g_bsum[tid] : 0;
    __syncthreads();
#pragma unroll
    for (int off = 1; off < 512; off <<= 1) {
        int t = (tid >= off) ? sh[tid - off] : 0;
        __syncthreads();
        sh[tid] += t;
        __syncthreads();
    }
    int i = blockIdx.x * 512 + tid;
    if (i == 0) { g_rowptr[0] = 0; g_cursor[0] = 0; }
    if (i < N) {
        int b = i >> 8;                    // scanA blocks are 256 wide
        int add = (b == 0) ? 0 : sh[b - 1];
        int v = g_rowptr[i + 1] + add;
        g_rowptr[i + 1] = v;
        if (i + 1 < N) g_cursor[i + 1] = v;
        g_dinv[i] = rsqrtf((float)g_cnt[i] + 1.0f);
    }
}

// ---------------- fill: re-decode raw edges, scatter src into CSR slot -------
__global__ void k_fill(const unsigned int* __restrict__ w, int E) {
    int e = blockIdx.x * blockDim.x + threadIdx.x;
    if (e >= E) return;
    int s, d;
    if (g_isI32) { s = (int)w[e];     d = (int)w[E + e]; }
    else         { s = (int)w[2 * e]; d = (int)w[2 * E + 2 * e]; }
    int pos = atomicAdd(&g_cursor[d], 1);
    g_eidx[pos] = s;
}

// ---------------- GEMM via HMMA mma.sync: 128 nodes/block --------------------
// bnmode 0: h = relu(x @ W_in + b_in)       (input MLP fused, layer 0)
// bnmode 1: h = relu(BN(g_hC; stats Lprev)) (later layers)
// Output: g_hBh[row][:] = half( dinv[row] * (h @ W)[row][:] ), fp32 accum.
__global__ void k_gemm(const float* __restrict__ W,
                       const float* __restrict__ gamma, const float* __restrict__ beta,
                       int Lprev, int bnmode, int N,
                       const float* __restrict__ x, const float* __restrict__ Win,
                       const float* __restrict__ bin) {
    __shared__ __half hs[GEMM_NODES * HS_STRIDE];   // 18.4 KB
    __shared__ __half Wt[HDIM * WT_STRIDE];         // 9.2 KB, Wt[n][k] = W[k][n]
    __shared__ float s_mu[HDIM], s_sc[HDIM], s_bt[HDIM];
    __shared__ float Wi[FIN * HDIM];
    __shared__ float bi[HDIM];
    __shared__ float xs[GEMM_NODES * FIN];
    int tid = threadIdx.x;
    int node0 = blockIdx.x * GEMM_NODES;
    int cnt = min(GEMM_NODES, N - node0);

    // stage W transposed to fp16 (i = k*64 + n)
    for (int i = tid; i < HDIM * HDIM; i += 256) {
        int k = i >> 6, n = i & 63;
        Wt[n * WT_STRIDE + k] = __float2half(W[i]);
    }

    if (bnmode) {
        if (tid < HDIM) {
            float invN = 1.0f / (float)N;
            float mu = g_sum[Lprev * HDIM + tid] * invN;
            float var = g_sumsq[Lprev * HDIM + tid] * invN - mu * mu;
            s_mu[tid] = mu;
            s_sc[tid] = gamma[Lprev * HDIM + tid] * rsqrtf(var + EPSV);
            s_bt[tid] = beta[Lprev * HDIM + tid];
        }
        __syncthreads();
        const float4* h4 = (const float4*)&g_hC[(size_t)node0 * HDIM];
        for (int i = tid; i < cnt * 16; i += 256) {      // 16 float4 per row
            float4 v = h4[i];
            int r = i >> 4, j = (i & 15) * 4;
            v.x = fmaxf((v.x - s_mu[j + 0]) * s_sc[j + 0] + s_bt[j + 0], 0.0f);
            v.y = fmaxf((v.y - s_mu[j + 1]) * s_sc[j + 1] + s_bt[j + 1], 0.0f);
            v.z = fmaxf((v.z - s_mu[j + 2]) * s_sc[j + 2] + s_bt[j + 2], 0.0f);
            v.w = fmaxf((v.w - s_mu[j + 3]) * s_sc[j + 3] + s_bt[j + 3], 0.0f);
            __half2* dst = (__half2*)&hs[r * HS_STRIDE + j];
            dst[0] = __floats2half2_rn(v.x, v.y);
            dst[1] = __floats2half2_rn(v.z, v.w);
        }
    } else {
        for (int i = tid; i < FIN * HDIM; i += 256) Wi[i] = Win[i];
        if (tid < HDIM) bi[tid] = bin[tid];
        for (int i = tid; i < cnt * FIN; i += 256) {
            int r = i / FIN, k = i % FIN;
            xs[i] = x[(size_t)(node0 + r) * FIN + k];
        }
        __syncthreads();
        for (int i = tid; i < cnt * HDIM; i += 256) {
            int r = i >> 6, j = i & 63;
            float acc = bi[j];
#pragma unroll
            for (int k = 0; k < FIN; k++) acc += xs[r * FIN + k] * Wi[k * HDIM + j];
            hs[r * HS_STRIDE + j] = __float2half(fmaxf(acc, 0.0f));
        }
    }
    __syncthreads();
    // (tail rows of hs beyond cnt hold garbage; their outputs are never stored)

    int lane = tid & 31, wid = tid >> 5;
    int rBase = wid * 16;          // 16 nodes per warp
    int r = lane >> 2;             // 0..7
    int m = lane & 3;              // 0..3
    float c[8][4];
#pragma unroll
    for (int nb = 0; nb < 8; nb++) { c[nb][0] = c[nb][1] = c[nb][2] = c[nb][3] = 0.0f; }

#pragma unroll
    for (int kc = 0; kc < 4; kc++) {
        int kb = kc * 16;
        uint32_t a0 = *(const uint32_t*)&hs[(rBase + r)     * HS_STRIDE + kb + 2 * m];
        uint32_t a1 = *(const uint32_t*)&hs[(rBase + r + 8) * HS_STRIDE + kb + 2 * m];
        uint32_t a2 = *(const uint32_t*)&hs[(rBase + r)     * HS_STRIDE + kb + 2 * m + 8];
        uint32_t a3 = *(const uint32_t*)&hs[(rBase + r + 8) * HS_STRIDE + kb + 2 * m + 8];
#pragma unroll
        for (int nb = 0; nb < 8; nb++) {
            int n = nb * 8 + r;    // B-frag column = t/4
            uint32_t b0 = *(const uint32_t*)&Wt[n * WT_STRIDE + kb + 2 * m];
            uint32_t b1 = *(const uint32_t*)&Wt[n * WT_STRIDE + kb + 2 * m + 8];
            asm volatile(
                "mma.sync.aligned.m16n8k16.row.col.f32.f16.f16.f32 "
                "{%0,%1,%2,%3}, {%4,%5,%6,%7}, {%8,%9}, {%0,%1,%2,%3};"
                : "+f"(c[nb][0]), "+f"(c[nb][1]), "+f"(c[nb][2]), "+f"(c[nb][3])
                : "r"(a0), "r"(a1), "r"(a2), "r"(a3), "r"(b0), "r"(b1));
        }
    }

    // epilogue: prescale by dinv, store fp16
    int row0 = node0 + rBase + r;
    int row1 = row0 + 8;
    float di0 = (row0 < N) ? g_dinv[row0] : 0.0f;
    float di1 = (row1 < N) ? g_dinv[row1] : 0.0f;
    __half2* out2 = (__half2*)g_hBh;
#pragma unroll
    for (int nb = 0; nb < 8; nb++) {
        if (row0 < N)
            out2[(size_t)row0 * 32 + nb * 4 + m] = __floats2half2_rn(c[nb][0] * di0, c[nb][1] * di0);
        if (row1 < N)
            out2[(size_t)row1 * 32 + nb * 4 + m] = __floats2half2_rn(c[nb][2] * di1, c[nb][3] * di1);
    }
}

// ---------------- pull aggregation: persistent, 2 edges per LDG.64 -----------
// warp = 2 half-warps x 16 lanes; lane loads uint2 (8B = 4 feats) of its edge's
// row; half-warp h handles edges i+h, i+2+h, ... ; fold via one shfl(16).
__global__ void k_agg(const float* __restrict__ bg, int L, int N) {
    __shared__ float s_s[HDIM];
    __shared__ float s_q[HDIM];
    int tid = threadIdx.x;
    int lane = tid & 31;
    int warp = tid >> 5;
    int hw = lane >> 4;     // half-warp 0/1
    int ol = lane & 15;     // 8B chunk within row (16 x uint2 = 128B)
    if (tid < HDIM) { s_s[tid] = 0.0f; s_q[tid] = 0.0f; }
    __syncthreads();
    // bias for the 4 features lane (hw==0) will finalize
    float4 bb = *(const float4*)&bg[L * HDIM + 4 * ol];
    float sx0 = 0.f, sx1 = 0.f, sx2 = 0.f, sx3 = 0.f;
    float qx0 = 0.f, qx1 = 0.f, qx2 = 0.f, qx3 = 0.f;
    const uint2* hB4 = (const uint2*)g_hBh;   // 16 uint2 per 64-half row
    for (int node = blockIdx.x * 8 + warp; node < N; node += AGG_BLOCKS * 8) {
        int r0 = g_rowptr[node];
        int r1 = g_rowptr[node + 1];
        float ddst = g_dinv[node];
        float a0 = 0.f, a1 = 0.f, a2 = 0.f, a3 = 0.f;
        int i = r0;
        for (; i + 8 <= r1; i += 8) {
            int sA = __ldg(&g_eidx[i + 0 + hw]);
            int sB = __ldg(&g_eidx[i + 2 + hw]);
            int sC = __ldg(&g_eidx[i + 4 + hw]);
            int sD = __ldg(&g_eidx[i + 6 + hw]);
            uint2 vA = __ldg(&hB4[(size_t)sA * 16 + ol]);
            uint2 vB = __ldg(&hB4[(size_t)sB * 16 + ol]);
            uint2 vC = __ldg(&hB4[(size_t)sC * 16 + ol]);
            uint2 vD = __ldg(&hB4[(size_t)sD * 16 + ol]);
            float2 f;
            f = __half22float2(*(__half2*)&vA.x); a0 += f.x; a1 += f.y;
            f = __half22float2(*(__half2*)&vA.y); a2 += f.x; a3 += f.y;
            f = __half22float2(*(__half2*)&vB.x); a0 += f.x; a1 += f.y;
            f = __half22float2(*(__half2*)&vB.y); a2 += f.x; a3 += f.y;
            f = __half22float2(*(__half2*)&vC.x); a0 += f.x; a1 += f.y;
            f = __half22float2(*(__half2*)&vC.y); a2 += f.x; a3 += f.y;
            f = __half22float2(*(__half2*)&vD.x); a0 += f.x; a1 += f.y;
            f = __half22float2(*(__half2*)&vD.y); a2 += f.x; a3 += f.y;
        }
        for (; i + 2 <= r1; i += 2) {
            int s = __ldg(&g_eidx[i + hw]);
            uint2 v = __ldg(&hB4[(size_t)s * 16 + ol]);
            float2 f;
            f = __half22float2(*(__half2*)&v.x); a0 += f.x; a1 += f.y;
            f = __half22float2(*(__half2*)&v.y); a2 += f.x; a3 += f.y;
        }
        if (i < r1 && hw == 0) {           // single leftover edge
            int s = __ldg(&g_eidx[i]);
            uint2 v = __ldg(&hB4[(size_t)s * 16 + ol]);
            float2 f;
            f = __half22float2(*(__half2*)&v.x); a0 += f.x; a1 += f.y;
            f = __half22float2(*(__half2*)&v.y); a2 += f.x; a3 += f.y;
        }
        // fold half-warp 1 into half-warp 0
        a0 += __shfl_down_sync(0xffffffffu, a0, 16);
        a1 += __shfl_down_sync(0xffffffffu, a1, 16);
        a2 += __shfl_down_sync(0xffffffffu, a2, 16);
        a3 += __shfl_down_sync(0xffffffffu, a3, 16);
        if (hw == 0) {
            uint2 hv = __ldg(&hB4[(size_t)node * 16 + ol]);   // self term
            float2 f0 = __half22float2(*(__half2*)&hv.x);
            float2 f1 = __half22float2(*(__half2*)&hv.y);
            float r0v = (a0 + f0.x) * ddst + bb.x;
            float r1v = (a1 + f0.y) * ddst + bb.y;
            float r2v = (a2 + f1.x) * ddst + bb.z;
            float r3v = (a3 + f1.y) * ddst + bb.w;
            ((float4*)g_hC)[(size_t)node * 16 + ol] = make_float4(r0v, r1v, r2v, r3v);
            sx0 += r0v; sx1 += r1v; sx2 += r2v; sx3 += r3v;
            qx0 += r0v * r0v; qx1 += r1v * r1v; qx2 += r2v * r2v; qx3 += r3v * r3v;
        }
    }
    if (hw == 0) {
        atomicAdd(&s_s[4 * ol + 0], sx0); atomicAdd(&s_q[4 * ol + 0], qx0);
        atomicAdd(&s_s[4 * ol + 1], sx1); atomicAdd(&s_q[4 * ol + 1], qx1);
        atomicAdd(&s_s[4 * ol + 2], sx2); atomicAdd(&s_q[4 * ol + 2], qx2);
        atomicAdd(&s_s[4 * ol + 3], sx3); atomicAdd(&s_q[4 * ol + 3], qx3);
    }
    __syncthreads();
    if (tid < HDIM) {
        atomicAdd(&g_sum[L * HDIM + tid],   s_s[tid]);
        atomicAdd(&g_sumsq[L * HDIM + tid], s_q[tid]);
    }
}

// ---------------- classifier with fused BN (no relu) on load ----------------
__global__ void k_cls(const float* __restrict__ Wc1, const float* __restrict__ bc1,
                      const float* __restrict__ Wc2, const float* __restrict__ bc2,
                      const float* __restrict__ gamma, const float* __restrict__ beta,
                      float* __restrict__ out, int N) {
    __shared__ float W1[HDIM * 32];
    __shared__ float b1[32];
    __shared__ float W2[32 * 2];
    __shared__ float b2v[2];
    __shared__ float s_mu[HDIM], s_sc[HDIM], s_bt[HDIM];
    __shared__ float hs[128 * 65];
    int tid = threadIdx.x;
    for (int i = tid; i < HDIM * 32; i += 128) W1[i] = Wc1[i];
    if (tid < 32) b1[tid] = bc1[tid];
    if (tid < 64) W2[tid] = Wc2[tid];
    if (tid < 2)  b2v[tid] = bc2[tid];
    if (tid < HDIM) {
        int Lp = NLAYERS - 1;
        float invN = 1.0f / (float)N;
        float mu = g_sum[Lp * HDIM + tid] * invN;
        float var = g_sumsq[Lp * HDIM + tid] * invN - mu * mu;
        s_mu[tid] = mu;
        s_sc[tid] = gamma[Lp * HDIM + tid] * rsqrtf(var + EPSV);
        s_bt[tid] = beta[Lp * HDIM + tid];
    }
    int node0 = blockIdx.x * 128;
    int cnt = min(128, N - node0);
    __syncthreads();
    for (int i = tid; i < cnt * HDIM; i += 128) {
        int r = i >> 6, k = i & 63;
        float v = g_hC[(size_t)(node0 + r) * HDIM + k];
        hs[r * 65 + k] = (v - s_mu[k]) * s_sc[k] + s_bt[k];
    }
    __syncthreads();
    int node = node0 + tid;
    if (node < N) {
        float o0 = b2v[0], o1 = b2v[1];
        const float* hr = &hs[tid * 65];
        for (int jj = 0; jj < 32; jj++) {
            float a = b1[jj];
#pragma unroll 8
            for (int k = 0; k < HDIM; k++) a += hr[k] * W1[k * 32 + jj];
            a = fmaxf(a, 0.0f);
            o0 += a * W2[jj * 2 + 0];
            o1 += a * W2[jj * 2 + 1];
        }
        out[node * 2 + 0] = o0;
        out[node * 2 + 1] = o1;
    }
}

// ---------------- launch -----------------------------------------------------
extern "C" void kernel_launch(void* const* d_in, const int* in_sizes, int n_in,
                              void* d_out, int out_size) {
    const float*        x     = (const float*)d_in[0];
    const unsigned int* ei    = (const unsigned int*)d_in[1];
    const float*        Win   = (const float*)d_in[2];
    const float*        bin   = (const float*)d_in[3];
    const float*        Wg    = (const float*)d_in[4];
    const float*        bg    = (const float*)d_in[5];
    const float*        gamma = (const float*)d_in[6];
    const float*        beta  = (const float*)d_in[7];
    const float*        Wc1   = (const float*)d_in[8];
    const float*        bc1   = (const float*)d_in[9];
    const float*        Wc2   = (const float*)d_in[10];
    const float*        bc2   = (const float*)d_in[11];
    float*              out   = (float*)d_out;

    int N = in_sizes[0] / FIN;
    int E = in_sizes[1] / 2;
    if (N > NMAX) N = NMAX;
    if (E > EMAX) E = EMAX;

    int gN = (N + 255) / 256;
    int gE = (E + 255) / 256;
    int nblocks = (N + SCAN_B - 1) / SCAN_B;
    int g512 = (N + 511) / 512;

    // ---- preprocessing: CSR build (5 launches) ----
    {
        int nwords = 2 * E;
        if (nwords > 8192) nwords = 8192;
        k_zd<<<gN, 256>>>(ei, nwords, N);
    }
    k_hist<<<gE, 256>>>(ei, E);
    k_scanA<<<nblocks, SCAN_B>>>(N);
    k_scanC<<<g512, 512>>>(nblocks, N);
    k_fill<<<gE, 256>>>(ei, E);

    // ---- network (7 launches) ----
    for (int L = 0; L < NLAYERS; L++) {
        k_gemm<<<(N + GEMM_NODES - 1) / GEMM_NODES, 256>>>(
            Wg + L * HDIM * HDIM, gamma, beta,
            L - 1, (L == 0) ? 0 : 1, N, x, Win, bin);
        k_agg<<<AGG_BLOCKS, 256>>>(bg, L, N);
    }
    k_cls<<<(N + 127) / 128, 128>>>(Wc1, bc1, Wc2, bc2, gamma, beta, out, N);
}